// round 6
// baseline (speedup 1.0000x reference)
#include <cuda_runtime.h>
#include <math.h>

// Problem constants (fixed by the dataset)
#define D        512      // class_dim
#define REL      53       // rel_num
#define NBAGS    16384
#define NSENT    131072
#define BLOCK    256
#define WARPS    (BLOCK / 32)
#define MAX_LEN  512      // safe upper bound on bag length (mean ~8, max ~25)

// GEMM kernel tiling
#define TB_BAGS  16       // bags per block in kernel 2
#define KC       64       // K chunk
#define RPAD     64       // rel dim padded
#define SPAD     68       // smem row stride (floats), keeps float4 alignment

// 32 MB scratch for bag representations (device-global: allowed)
__device__ float g_bag[NBAGS * D];

// Flag: 1 if scope/X_Rel buffers hold int64, 0 if int32.
__device__ int g_idx64;

__global__ void detect_idx_dtype(const int* __restrict__ scope_as_i32) {
    // int64 little-endian: word 1 = high word of start0 (=0)  -> 0
    // int32:               word 1 = end0 (>=1)                -> nonzero
    g_idx64 = (scope_as_i32[1] == 0) ? 1 : 0;
}

// ---------------------------------------------------------------------------
// Kernel 1: per-bag attention -> bag vector
// ---------------------------------------------------------------------------
__global__ __launch_bounds__(BLOCK)
void tan_bag_kernel(const float* __restrict__ X,
                    const void*  __restrict__ scope_raw,     // [B,2] i32 or i64
                    const float* __restrict__ Constraints,   // [REL,D]
                    const void*  __restrict__ xrel_raw)      // [B]   i32 or i64
{
    const int b    = blockIdx.x;
    const int tid  = threadIdx.x;
    const int lane = tid & 31;
    const int warp = tid >> 5;

    __shared__ float sCon[D];
    __shared__ float sScores[MAX_LEN];

    long long s64, e64, r64;
    if (g_idx64) {
        const long long* sc = (const long long*)scope_raw;
        s64 = sc[2 * b];
        e64 = sc[2 * b + 1];
        r64 = ((const long long*)xrel_raw)[b];
    } else {
        const int* sc = (const int*)scope_raw;
        s64 = sc[2 * b];
        e64 = sc[2 * b + 1];
        r64 = ((const int*)xrel_raw)[b];
    }
    // Defensive clamps: a wrong dtype guess yields rel_err, never an IMA.
    if (s64 < 0) s64 = 0;
    if (s64 > NSENT) s64 = NSENT;
    if (e64 < s64) e64 = s64;
    if (e64 > NSENT) e64 = NSENT;
    if (r64 < 0) r64 = 0;
    if (r64 >= REL) r64 = REL - 1;
    const int start = (int)s64;
    int len = (int)(e64 - s64);
    if (len > MAX_LEN) len = MAX_LEN;
    const int rel = (int)r64;

    // ---- Phase 1: stage query vector Con = Constraints[rel] into smem ----
    {
        const float4* __restrict__ Con4 = (const float4*)(Constraints + (long long)rel * D);
        float4* sCon4 = (float4*)sCon;
        for (int i = tid; i < D / 4; i += BLOCK) sCon4[i] = Con4[i];
    }
    __syncthreads();

    // ---- Phase 2: scores[s] = dot(X[start+s], Con), one warp per sentence ----
    // Single HBM pass over X (268 MB) — the kernel's roofline term.
    {
        // hoist the lane-invariant Con fragment into registers
        const float4* sCon4 = (const float4*)sCon;
        float4 c0 = sCon4[lane];
        float4 c1 = sCon4[lane + 32];
        float4 c2 = sCon4[lane + 64];
        float4 c3 = sCon4[lane + 96];
        for (int s = warp; s < len; s += WARPS) {
            const float4* __restrict__ row =
                (const float4*)(X + (long long)(start + s) * D);
            float4 x0 = row[lane];
            float4 x1 = row[lane + 32];
            float4 x2 = row[lane + 64];
            float4 x3 = row[lane + 96];
            float acc = x0.x * c0.x + x0.y * c0.y + x0.z * c0.z + x0.w * c0.w;
            acc = fmaf(x1.x, c1.x, fmaf(x1.y, c1.y, fmaf(x1.z, c1.z, fmaf(x1.w, c1.w, acc))));
            acc = fmaf(x2.x, c2.x, fmaf(x2.y, c2.y, fmaf(x2.z, c2.z, fmaf(x2.w, c2.w, acc))));
            acc = fmaf(x3.x, c3.x, fmaf(x3.y, c3.y, fmaf(x3.z, c3.z, fmaf(x3.w, c3.w, acc))));
            #pragma unroll
            for (int off = 16; off; off >>= 1)
                acc += __shfl_xor_sync(0xffffffffu, acc, off);
            if (lane == 0) sScores[s] = acc;
        }
    }
    __syncthreads();

    // ---- Phase 3: softmax over the bag (warp 0; len is small) ----
    if (warp == 0) {
        float m = -INFINITY;
        for (int s = lane; s < len; s += 32) m = fmaxf(m, sScores[s]);
        #pragma unroll
        for (int off = 16; off; off >>= 1)
            m = fmaxf(m, __shfl_xor_sync(0xffffffffu, m, off));
        float sum = 0.f;
        for (int s = lane; s < len; s += 32) {
            float e = expf(sScores[s] - m);
            sScores[s] = e;
            sum += e;
        }
        #pragma unroll
        for (int off = 16; off; off >>= 1)
            sum += __shfl_xor_sync(0xffffffffu, sum, off);
        float inv = 1.f / sum;
        for (int s = lane; s < len; s += 32) sScores[s] *= inv;
    }
    __syncthreads();

    // ---- Phase 4: bag = sum_s w[s] * X[start+s]  (rows L2-hot; unrolled x4) ----
    {
        float2 acc = make_float2(0.f, 0.f);
        const float2* __restrict__ X2 = (const float2*)X;
        long long base = (long long)start * (D / 2) + tid;
        int s = 0;
        for (; s + 4 <= len; s += 4) {
            float w0 = sScores[s + 0], w1 = sScores[s + 1];
            float w2 = sScores[s + 2], w3 = sScores[s + 3];
            float2 x0 = X2[base + (long long)(s + 0) * (D / 2)];
            float2 x1 = X2[base + (long long)(s + 1) * (D / 2)];
            float2 x2 = X2[base + (long long)(s + 2) * (D / 2)];
            float2 x3 = X2[base + (long long)(s + 3) * (D / 2)];
            acc.x = fmaf(w0, x0.x, acc.x); acc.y = fmaf(w0, x0.y, acc.y);
            acc.x = fmaf(w1, x1.x, acc.x); acc.y = fmaf(w1, x1.y, acc.y);
            acc.x = fmaf(w2, x2.x, acc.x); acc.y = fmaf(w2, x2.y, acc.y);
            acc.x = fmaf(w3, x3.x, acc.x); acc.y = fmaf(w3, x3.y, acc.y);
        }
        for (; s < len; s++) {
            float w = sScores[s];
            float2 x = X2[base + (long long)s * (D / 2)];
            acc.x = fmaf(w, x.x, acc.x);
            acc.y = fmaf(w, x.y, acc.y);
        }
        ((float2*)(g_bag + (long long)b * D))[tid] = acc;
    }
}

// ---------------------------------------------------------------------------
// Kernel 2: out[16384,53] = bag @ W_cls^T + b_cls  (tiled fp32 GEMM)
// Block: 256 threads, 16 bags x 64 rels (padded); thread: 1 bag x 4 rels.
// ---------------------------------------------------------------------------
__global__ __launch_bounds__(BLOCK)
void tan_gemm_kernel(const float* __restrict__ W_cls,   // [REL,D]
                     const float* __restrict__ b_cls,   // [REL]
                     float* __restrict__ out)           // [B,REL]
{
    __shared__ float sA[TB_BAGS][SPAD];   // bag tile   16 x 64 (+pad)
    __shared__ float sB[RPAD][SPAD];      // W tile     64 x 64 (+pad)

    const int tid  = threadIdx.x;
    const int tx   = tid & 15;            // rel group: rels tx*4 .. tx*4+3
    const int ty   = tid >> 4;            // bag index within tile: 0..15
    const int bag0 = blockIdx.x * TB_BAGS;

    float acc0 = 0.f, acc1 = 0.f, acc2 = 0.f, acc3 = 0.f;

    for (int k0 = 0; k0 < D; k0 += KC) {
        // load bag tile: 16 rows x 16 float4 -> one float4 per thread
        {
            int r = tid >> 4, c = tid & 15;
            *(float4*)&sA[r][c * 4] =
                *(const float4*)&g_bag[(long long)(bag0 + r) * D + k0 + c * 4];
        }
        // load W tile: 64 rows x 16 float4 -> four float4 per thread (zero-pad r>=53)
        #pragma unroll
        for (int i = 0; i < 4; i++) {
            int idx = tid + i * 256;
            int r = idx >> 4, c = idx & 15;
            float4 v = make_float4(0.f, 0.f, 0.f, 0.f);
            if (r < REL)
                v = *(const float4*)&W_cls[(long long)r * D + k0 + c * 4];
            *(float4*)&sB[r][c * 4] = v;
        }
        __syncthreads();

        #pragma unroll
        for (int k4 = 0; k4 < KC / 4; k4++) {
            float4 a = *(const float4*)&sA[ty][k4 * 4];
            float4 b0 = *(const float4*)&sB[tx * 4 + 0][k4 * 4];
            float4 b1 = *(const float4*)&sB[tx * 4 + 1][k4 * 4];
            float4 b2 = *(const float4*)&sB[tx * 4 + 2][k4 * 4];
            float4 b3 = *(const float4*)&sB[tx * 4 + 3][k4 * 4];
            acc0 = fmaf(a.x, b0.x, fmaf(a.y, b0.y, fmaf(a.z, b0.z, fmaf(a.w, b0.w, acc0))));
            acc1 = fmaf(a.x, b1.x, fmaf(a.y, b1.y, fmaf(a.z, b1.z, fmaf(a.w, b1.w, acc1))));
            acc2 = fmaf(a.x, b2.x, fmaf(a.y, b2.y, fmaf(a.z, b2.z, fmaf(a.w, b2.w, acc2))));
            acc3 = fmaf(a.x, b3.x, fmaf(a.y, b3.y, fmaf(a.z, b3.z, fmaf(a.w, b3.w, acc3))));
        }
        __syncthreads();
    }

    const int bag = bag0 + ty;
    const int r0  = tx * 4;
    float* o = out + (long long)bag * REL;
    if (r0 + 0 < REL) o[r0 + 0] = acc0 + b_cls[r0 + 0];
    if (r0 + 1 < REL) o[r0 + 1] = acc1 + b_cls[r0 + 1];
    if (r0 + 2 < REL) o[r0 + 2] = acc2 + b_cls[r0 + 2];
    if (r0 + 3 < REL) o[r0 + 3] = acc3 + b_cls[r0 + 3];
}

extern "C" void kernel_launch(void* const* d_in, const int* in_sizes, int n_in,
                              void* d_out, int out_size) {
    // metadata order: X, X_Scope, Constraints, X_Rel, W_cls, b_cls
    const float* X     = (const float*)d_in[0];
    const void*  scope = d_in[1];
    const float* Con   = (const float*)d_in[2];
    const void*  xrel  = d_in[3];
    const float* Wc    = (const float*)d_in[4];
    const float* bc    = (const float*)d_in[5];
    float*       out   = (float*)d_out;

    detect_idx_dtype<<<1, 1>>>((const int*)scope);
    tan_bag_kernel<<<NBAGS, BLOCK>>>(X, scope, Con, xrel);
    tan_gemm_kernel<<<NBAGS / TB_BAGS, BLOCK>>>(Wc, bc, out);
}

// round 7
// speedup vs baseline: 2.8694x; 2.8694x over previous
#include <cuda_runtime.h>
#include <math.h>

// Problem constants (fixed by the dataset)
#define D        512      // class_dim
#define REL      53       // rel_num
#define NBAGS    16384
#define NSENT    131072
#define BLOCK    256
#define WARPS    (BLOCK / 32)
#define MAX_LEN  512      // hard safety cap on bag length (mean ~8)
#define STAGE    16       // rows staged in smem (P(len>16) ~ 0)

// GEMM tiling (kernel 2)
#define MB       64       // bags per block
#define RPAD     64       // rels padded (53 real)
#define KC       32       // K chunk
#define S2       68       // smem row stride (floats); k-major tiles

// 32 MB scratch for bag representations (device-global: allowed)
__device__ float g_bag[NBAGS * D];

// ---------------------------------------------------------------------------
// Kernel 1: per-bag attention -> bag vector (dtype detect inlined)
// ---------------------------------------------------------------------------
__global__ __launch_bounds__(BLOCK)
void tan_bag_kernel(const float* __restrict__ X,
                    const void*  __restrict__ scope_raw,     // [B,2] i32 or i64
                    const float* __restrict__ Constraints,   // [REL,D]
                    const void*  __restrict__ xrel_raw)      // [B]   i32 or i64
{
    const int b    = blockIdx.x;
    const int tid  = threadIdx.x;
    const int lane = tid & 31;
    const int warp = tid >> 5;

    __shared__ float sX[STAGE][D];        // 32 KB row staging
    __shared__ float sCon[D];             // 2 KB
    __shared__ float sScores[MAX_LEN];    // 2 KB

    // Inline dtype detect: int64-LE => word1 (hi word of start0=0) == 0;
    // int32 => word1 = end0 >= 1 (bags nonempty). L1/L2-hot load.
    const int* sc32 = (const int*)scope_raw;
    const bool idx64 = (sc32[1] == 0);

    long long s64, e64, r64;
    if (idx64) {
        const long long* sc = (const long long*)scope_raw;
        s64 = sc[2 * b];
        e64 = sc[2 * b + 1];
        r64 = ((const long long*)xrel_raw)[b];
    } else {
        s64 = sc32[2 * b];
        e64 = sc32[2 * b + 1];
        r64 = ((const int*)xrel_raw)[b];
    }
    // Defensive clamps: a wrong guess yields rel_err, never an IMA.
    if (s64 < 0) s64 = 0;
    if (s64 > NSENT) s64 = NSENT;
    if (e64 < s64) e64 = s64;
    if (e64 > NSENT) e64 = NSENT;
    if (r64 < 0) r64 = 0;
    if (r64 >= REL) r64 = REL - 1;
    const int start = (int)s64;
    int len = (int)(e64 - s64);
    if (len > MAX_LEN) len = MAX_LEN;
    const int rel = (int)r64;

    // ---- Phase 1: stage query vector Con = Constraints[rel] ----
    {
        const float4* __restrict__ Con4 = (const float4*)(Constraints + (long long)rel * D);
        float4* sCon4 = (float4*)sCon;
        for (int i = tid; i < D / 4; i += BLOCK) sCon4[i] = Con4[i];
    }
    __syncthreads();

    // ---- Phase 2: scores + stage rows to smem (single HBM pass over X) ----
    {
        const float4* sCon4 = (const float4*)sCon;
        float4 c0 = sCon4[lane];
        float4 c1 = sCon4[lane + 32];
        float4 c2 = sCon4[lane + 64];
        float4 c3 = sCon4[lane + 96];
        for (int s = warp; s < len; s += WARPS) {
            const float4* __restrict__ row =
                (const float4*)(X + (long long)(start + s) * D);
            float4 x0 = row[lane];
            float4 x1 = row[lane + 32];
            float4 x2 = row[lane + 64];
            float4 x3 = row[lane + 96];
            if (s < STAGE) {                 // stage for phase 4
                float4* sx = (float4*)sX[s];
                sx[lane]      = x0;
                sx[lane + 32] = x1;
                sx[lane + 64] = x2;
                sx[lane + 96] = x3;
            }
            float acc = x0.x * c0.x + x0.y * c0.y + x0.z * c0.z + x0.w * c0.w;
            acc = fmaf(x1.x, c1.x, fmaf(x1.y, c1.y, fmaf(x1.z, c1.z, fmaf(x1.w, c1.w, acc))));
            acc = fmaf(x2.x, c2.x, fmaf(x2.y, c2.y, fmaf(x2.z, c2.z, fmaf(x2.w, c2.w, acc))));
            acc = fmaf(x3.x, c3.x, fmaf(x3.y, c3.y, fmaf(x3.z, c3.z, fmaf(x3.w, c3.w, acc))));
            #pragma unroll
            for (int off = 16; off; off >>= 1)
                acc += __shfl_xor_sync(0xffffffffu, acc, off);
            if (lane == 0) sScores[s] = acc;
        }
    }
    __syncthreads();

    // ---- Phase 3: softmax over the bag (warp 0) ----
    if (warp == 0) {
        float m = -INFINITY;
        for (int s = lane; s < len; s += 32) m = fmaxf(m, sScores[s]);
        #pragma unroll
        for (int off = 16; off; off >>= 1)
            m = fmaxf(m, __shfl_xor_sync(0xffffffffu, m, off));
        float sum = 0.f;
        for (int s = lane; s < len; s += 32) {
            float e = expf(sScores[s] - m);
            sScores[s] = e;
            sum += e;
        }
        #pragma unroll
        for (int off = 16; off; off >>= 1)
            sum += __shfl_xor_sync(0xffffffffu, sum, off);
        float inv = 1.f / sum;
        for (int s = lane; s < len; s += 32) sScores[s] *= inv;
    }
    __syncthreads();

    // ---- Phase 4: bag = sum_s w[s] * row_s   (rows from smem; LDS not L2) ----
    {
        float2 acc = make_float2(0.f, 0.f);
        const int nst = (len < STAGE) ? len : STAGE;
        for (int s = 0; s < nst; s++) {
            float w = sScores[s];
            float2 x = ((const float2*)sX[s])[tid];
            acc.x = fmaf(w, x.x, acc.x);
            acc.y = fmaf(w, x.y, acc.y);
        }
        // rare overflow rows (len > STAGE): re-read from global (L2-hot)
        for (int s = nst; s < len; s++) {
            float w = sScores[s];
            float2 x = ((const float2*)(X + (long long)(start + s) * D))[tid];
            acc.x = fmaf(w, x.x, acc.x);
            acc.y = fmaf(w, x.y, acc.y);
        }
        ((float2*)(g_bag + (long long)b * D))[tid] = acc;
    }
}

// ---------------------------------------------------------------------------
// Kernel 2: out[16384,53] = bag @ W_cls^T + b_cls
// k-major smem tiles (conflict-light), 64 bags x 64 rels / block, 256 blocks.
// Thread (tx,ty) computes bags ty*4..+3  x  rels tx*4..+3  (16 accumulators).
// ---------------------------------------------------------------------------
__global__ __launch_bounds__(BLOCK)
void tan_gemm_kernel(const float* __restrict__ W_cls,   // [REL,D]
                     const float* __restrict__ b_cls,   // [REL]
                     float* __restrict__ out)           // [B,REL]
{
    __shared__ float sA[KC][S2];   // k-major bag tile:  sA[k][bag]
    __shared__ float sB[KC][S2];   // k-major W tile:    sB[k][rel]

    const int tid  = threadIdx.x;
    const int tx   = tid & 15;     // rel group
    const int ty   = tid >> 4;     // bag group
    const int bag0 = blockIdx.x * MB;

    float acc[4][4];
    #pragma unroll
    for (int i = 0; i < 4; i++)
        #pragma unroll
        for (int j = 0; j < 4; j++) acc[i][j] = 0.f;

    for (int k0 = 0; k0 < D; k0 += KC) {
        // load + transpose bag tile: 64 bags x 8 float4-cols = 512 float4
        #pragma unroll
        for (int i = 0; i < 2; i++) {
            int idx = tid + i * BLOCK;          // 0..511
            int bag = idx >> 3;                 // 0..63
            int c   = idx & 7;                  // float4 col in chunk
            float4 v = *(const float4*)&g_bag[(long long)(bag0 + bag) * D + k0 + c * 4];
            sA[c * 4 + 0][bag] = v.x;
            sA[c * 4 + 1][bag] = v.y;
            sA[c * 4 + 2][bag] = v.z;
            sA[c * 4 + 3][bag] = v.w;
        }
        // load + transpose W tile (zero-pad rels >= 53)
        #pragma unroll
        for (int i = 0; i < 2; i++) {
            int idx = tid + i * BLOCK;
            int r   = idx >> 3;                 // 0..63
            int c   = idx & 7;
            float4 v = make_float4(0.f, 0.f, 0.f, 0.f);
            if (r < REL)
                v = *(const float4*)&W_cls[(long long)r * D + k0 + c * 4];
            sB[c * 4 + 0][r] = v.x;
            sB[c * 4 + 1][r] = v.y;
            sB[c * 4 + 2][r] = v.z;
            sB[c * 4 + 3][r] = v.w;
        }
        __syncthreads();

        #pragma unroll
        for (int k = 0; k < KC; k++) {
            float4 a = *(const float4*)&sA[k][ty * 4];   // 4 bags (broadcast)
            float4 bb = *(const float4*)&sB[k][tx * 4];  // 4 rels (2-way max)
            float av[4] = {a.x, a.y, a.z, a.w};
            float bv[4] = {bb.x, bb.y, bb.z, bb.w};
            #pragma unroll
            for (int i = 0; i < 4; i++)
                #pragma unroll
                for (int j = 0; j < 4; j++)
                    acc[i][j] = fmaf(av[i], bv[j], acc[i][j]);
        }
        __syncthreads();
    }

    // epilogue: 4 bags x 4 rels per thread
    #pragma unroll
    for (int i = 0; i < 4; i++) {
        const int bag = bag0 + ty * 4 + i;
        float* o = out + (long long)bag * REL;
        #pragma unroll
        for (int j = 0; j < 4; j++) {
            int r = tx * 4 + j;
            if (r < REL) o[r] = acc[i][j] + b_cls[r];
        }
    }
}

extern "C" void kernel_launch(void* const* d_in, const int* in_sizes, int n_in,
                              void* d_out, int out_size) {
    // metadata order: X, X_Scope, Constraints, X_Rel, W_cls, b_cls
    const float* X     = (const float*)d_in[0];
    const void*  scope = d_in[1];
    const float* Con   = (const float*)d_in[2];
    const void*  xrel  = d_in[3];
    const float* Wc    = (const float*)d_in[4];
    const float* bc    = (const float*)d_in[5];
    float*       out   = (float*)d_out;

    tan_bag_kernel<<<NBAGS, BLOCK>>>(X, scope, Con, xrel);
    tan_gemm_kernel<<<NBAGS / MB, BLOCK>>>(Wc, bc, out);
}